// round 12
// baseline (speedup 1.0000x reference)
#include <cuda_runtime.h>
#include <cuda_fp16.h>
#include <math.h>
#include <stdint.h>

#define N_NODES 50000
#define FEAT    128
#define MAX_E   800000
#define SCAN_TILE 4096
#define SCAN_NT ((N_NODES + SCAN_TILE - 1) / SCAN_TILE)   // 13

// ---- scratch (static __device__ arrays; no runtime allocation) ----
__device__ __half g_bufT[N_NODES * FEAT];   // post-GEMM features (fp16)
__device__ __half g_bufH[N_NODES * FEAT];   // post-agg features (fp16)
__device__ __half g_xh[N_NODES * FEAT];     // fp16 copy of input x
__device__ int   g_deg[N_NODES];
__device__ float g_dis[N_NODES];
__device__ int   g_rowoff[N_NODES + 1];
__device__ int   g_rank[MAX_E];             // per-edge rank within its dst list
__device__ int2  g_csr2[MAX_E];             // (src, dis[src]) per edge
__device__ unsigned long long g_tilestate[SCAN_NT];

// ================= input conversion =================
__global__ void k_x2h(const float* __restrict__ x, __half* __restrict__ xh, int n) {
    int i = (blockIdx.x * blockDim.x + threadIdx.x) * 8;
    if (i + 7 < n) {
        float4 f0 = *(const float4*)&x[i];
        float4 f1 = *(const float4*)&x[i + 4];
        uint4 o;
        __half2 h0 = __floats2half2_rn(f0.x, f0.y);
        __half2 h1 = __floats2half2_rn(f0.z, f0.w);
        __half2 h2 = __floats2half2_rn(f1.x, f1.y);
        __half2 h3 = __floats2half2_rn(f1.z, f1.w);
        o.x = *(uint32_t*)&h0; o.y = *(uint32_t*)&h1;
        o.z = *(uint32_t*)&h2; o.w = *(uint32_t*)&h3;
        *(uint4*)&xh[i] = o;
    }
}

// ================= CSR construction =================
// pass 1: count in-degree AND record each edge's rank within its dst bucket
__global__ void k_count(const int* __restrict__ dst, int E) {
    int i = (blockIdx.x * blockDim.x + threadIdx.x) * 4;
    if (i + 3 < E) {
        int4 d = *(const int4*)&dst[i];
        int4 r;
        r.x = atomicAdd(&g_deg[d.x], 1);
        r.y = atomicAdd(&g_deg[d.y], 1);
        r.z = atomicAdd(&g_deg[d.z], 1);
        r.w = atomicAdd(&g_deg[d.w], 1);
        *(int4*)&g_rank[i] = r;
    } else {
        for (int j = i; j < E; j++) g_rank[j] = atomicAdd(&g_deg[dst[j]], 1);
    }
}

// decoupled-lookback scan: rowoff = exclusive scan of deg; also dis = rsqrt(deg+1)
__global__ __launch_bounds__(1024) void k_scan_dl() {
    __shared__ int sh_w[32];
    __shared__ unsigned int sh_prefix;
    int tid = threadIdx.x, lane = tid & 31, wid = tid >> 5;
    int tile = blockIdx.x;
    int i0 = tile * SCAN_TILE + tid * 4;

    int4 v = make_int4(0, 0, 0, 0);
    if (i0 < N_NODES) {
        v = *(const int4*)&g_deg[i0];
        float4 d;
        d.x = rsqrtf((float)(v.x + 1));
        d.y = rsqrtf((float)(v.y + 1));
        d.z = rsqrtf((float)(v.z + 1));
        d.w = rsqrtf((float)(v.w + 1));
        *(float4*)&g_dis[i0] = d;
    }
    int t0 = v.x, t1 = t0 + v.y, t2 = t1 + v.z, t3 = t2 + v.w;
    int sc = t3;
    #pragma unroll
    for (int d = 1; d < 32; d <<= 1) {
        int t = __shfl_up_sync(0xffffffffu, sc, d);
        if (lane >= d) sc += t;
    }
    if (lane == 31) sh_w[wid] = sc;
    __syncthreads();
    if (wid == 0) {
        int ws = sh_w[lane];
        #pragma unroll
        for (int d = 1; d < 32; d <<= 1) {
            int t = __shfl_up_sync(0xffffffffu, ws, d);
            if (lane >= d) ws += t;
        }
        sh_w[lane] = ws;
    }
    __syncthreads();
    int total = sh_w[31];
    int thr_excl = (wid ? sh_w[wid - 1] : 0) + sc - t3;

    if (tid == 0) {
        unsigned long long st = ((tile == 0) ? (2ULL << 32) : (1ULL << 32)) | (unsigned)total;
        atomicExch(&g_tilestate[tile], st);
    }
    if (wid == 0) {
        unsigned int prefix = 0;
        if (tile > 0) {
            bool have = lane < tile;
            unsigned long long s = 0;
            if (have) {
                do { s = *(volatile unsigned long long*)&g_tilestate[tile - 1 - lane]; }
                while ((unsigned)(s >> 32) == 0u);
            }
            unsigned flag = (unsigned)(s >> 32);
            unsigned mask = __ballot_sync(0xffffffffu, have && flag == 2u);
            int firstInc = __ffs(mask) - 1;   // exists: tile 0 is always INCLUSIVE
            unsigned contrib = (have && lane <= firstInc) ? (unsigned)s : 0u;
            #pragma unroll
            for (int d = 16; d; d >>= 1) contrib += __shfl_xor_sync(0xffffffffu, contrib, d);
            prefix = contrib;
            if (lane == 0)
                atomicExch(&g_tilestate[tile], (2ULL << 32) | (unsigned)(prefix + (unsigned)total));
        }
        if (lane == 0) sh_prefix = prefix;
    }
    __syncthreads();
    int base = (int)sh_prefix + thr_excl;
    if (i0 < N_NODES) {
        int4 o = make_int4(base, base + t0, base + t1, base + t2);
        *(int4*)&g_rowoff[i0] = o;
    }
    if (tile == SCAN_NT - 1 && tid == 0) g_rowoff[N_NODES] = (int)sh_prefix + total;
}

// pass 2 (no atomics): scatter (src, dis[src]) to rowoff[dst] + rank
__global__ void k_fill(const int* __restrict__ src, const int* __restrict__ dst, int E) {
    int i = (blockIdx.x * blockDim.x + threadIdx.x) * 4;
    if (i + 3 < E) {
        int4 s = *(const int4*)&src[i];
        int4 d = *(const int4*)&dst[i];
        int4 r = *(const int4*)&g_rank[i];
        float f0 = g_dis[s.x], f1 = g_dis[s.y], f2 = g_dis[s.z], f3 = g_dis[s.w];
        int p0 = g_rowoff[d.x] + r.x;
        int p1 = g_rowoff[d.y] + r.y;
        int p2 = g_rowoff[d.z] + r.z;
        int p3 = g_rowoff[d.w] + r.w;
        g_csr2[p0] = make_int2(s.x, __float_as_int(f0));
        g_csr2[p1] = make_int2(s.y, __float_as_int(f1));
        g_csr2[p2] = make_int2(s.z, __float_as_int(f2));
        g_csr2[p3] = make_int2(s.w, __float_as_int(f3));
    } else {
        for (int j = i; j < E; j++) {
            int sj = src[j];
            int p = g_rowoff[dst[j]] + g_rank[j];
            g_csr2[p] = make_int2(sj, __float_as_int(g_dis[sj]));
        }
    }
}

// ================= fp16 single-pass GEMM via warp mma.sync ==============
// C[nrows,128] = A16[nrows,128] @ W16[128,128], fp32 accum, fp16 out.
// 256 threads / 8 warps / block; tile 128x128; warp owns 16 rows x 128 cols.
// ALL A-fragment loads hoisted above the kstep loop (MLP=32).
#define WROW 72

__device__ __forceinline__ uint32_t pack_h2(__half a, __half b) {
    __half2 h = __halves2half2(a, b);
    return *(uint32_t*)&h;
}
__device__ __forceinline__ void mma_f16(float* c, const uint32_t* a, uint32_t b0, uint32_t b1) {
    asm volatile(
        "mma.sync.aligned.m16n8k16.row.col.f32.f16.f16.f32 "
        "{%0,%1,%2,%3}, {%4,%5,%6,%7}, {%8,%9}, {%0,%1,%2,%3};"
        : "+f"(c[0]), "+f"(c[1]), "+f"(c[2]), "+f"(c[3])
        : "r"(a[0]), "r"(a[1]), "r"(a[2]), "r"(a[3]), "r"(b0), "r"(b1));
}
__device__ __forceinline__ void stage_W(uint32_t* Wh, const float* __restrict__ W, int tid) {
    for (int idx = tid; idx < 64 * 128; idx += 256) {
        int p = idx >> 7, n = idx & 127;
        int k = p * 2;
        float w0 = W[k * FEAT + n];
        float w1 = W[(k + 1) * FEAT + n];
        int kstep = p >> 3, q = p & 7;
        int word = n * WROW + kstep * 8 + (q & 3) * 2 + (q >> 2);
        Wh[word] = pack_h2(__float2half_rn(w0), __float2half_rn(w1));
    }
}

__global__ __launch_bounds__(256) void k_gemm_h(const __half* __restrict__ A,
                                                const float* __restrict__ W,
                                                __half* __restrict__ C, int nrows) {
    __shared__ uint32_t Wh[128 * WROW];
    int tid = threadIdx.x, wid = tid >> 5, lane = tid & 31;
    int g = lane >> 2, t = lane & 3;
    stage_W(Wh, W, tid);

    int r0 = blockIdx.x * 128 + wid * 16 + g;
    int r1 = r0 + 8;
    bool v0 = r0 < nrows, v1 = r1 < nrows;

    // hoist ALL A loads: 32 independent LDG.32 in flight
    uint32_t a[8][4];
    #pragma unroll
    for (int kstep = 0; kstep < 8; kstep++) {
        int ka = kstep * 16 + 2 * t;
        a[kstep][0] = v0 ? *(const uint32_t*)&A[r0 * FEAT + ka]     : 0u;
        a[kstep][1] = v1 ? *(const uint32_t*)&A[r1 * FEAT + ka]     : 0u;
        a[kstep][2] = v0 ? *(const uint32_t*)&A[r0 * FEAT + ka + 8] : 0u;
        a[kstep][3] = v1 ? *(const uint32_t*)&A[r1 * FEAT + ka + 8] : 0u;
    }
    __syncthreads();

    float acc[16][4];
    #pragma unroll
    for (int n0 = 0; n0 < 16; n0++)
        #pragma unroll
        for (int j = 0; j < 4; j++) acc[n0][j] = 0.0f;

    #pragma unroll
    for (int kstep = 0; kstep < 8; kstep++) {
        int bword = g * WROW + kstep * 8 + t * 2;
        #pragma unroll
        for (int n0 = 0; n0 < 16; n0++) {
            uint2 bh = *(const uint2*)&Wh[n0 * 8 * WROW + bword];
            mma_f16(acc[n0], a[kstep], bh.x, bh.y);
        }
    }

    #pragma unroll
    for (int n0 = 0; n0 < 16; n0++) {
        int col = n0 * 8 + 2 * t;
        if (v0) *(__half2*)&C[r0 * FEAT + col] = __floats2half2_rn(acc[n0][0], acc[n0][1]);
        if (v1) *(__half2*)&C[r1 * FEAT + col] = __floats2half2_rn(acc[n0][2], acc[n0][3]);
    }
}

// ================= aggregation (one warp per dst node, packed CSR) =======
__device__ __forceinline__ float elu1(float v) { return v > 0.0f ? v : expm1f(v); }

__device__ __forceinline__ float4 ld_row_h(const __half* __restrict__ T, int s, int lane) {
    uint2 u = *(const uint2*)(T + s * FEAT + lane * 4);
    __half2 h0 = *(__half2*)&u.x;
    __half2 h1 = *(__half2*)&u.y;
    float2 f0 = __half22float2(h0);
    float2 f1 = __half22float2(h1);
    return make_float4(f0.x, f0.y, f1.x, f1.y);
}

// FUSE_FINAL=0: Hout = fp16(ELU(acc+bias)). FUSE_FINAL=1: out = ELU(acc+bias)@Wl + bl.
template<int FUSE_FINAL>
__global__ __launch_bounds__(256) void k_agg_t(const __half* __restrict__ T,
                                               const float* __restrict__ bias,
                                               __half* __restrict__ Hout,
                                               const float* __restrict__ Wl,
                                               const float* __restrict__ bl,
                                               float* __restrict__ out) {
    int warp = (int)((blockIdx.x * blockDim.x + threadIdx.x) >> 5);
    int lane = threadIdx.x & 31;
    if (warp >= N_NODES) return;
    int node = warp;
    float dd = g_dis[node];

    float4 acc = ld_row_h(T, node, lane);
    float ws = dd * dd;                        // self-loop weight
    acc.x *= ws; acc.y *= ws; acc.z *= ws; acc.w *= ws;

    int beg = g_rowoff[node];
    int end = g_rowoff[node + 1];
    int e = beg;
    for (; e + 3 < end; e += 4) {
        int2 p0 = g_csr2[e],     p1 = g_csr2[e + 1];
        int2 p2 = g_csr2[e + 2], p3 = g_csr2[e + 3];
        float w0 = __int_as_float(p0.y) * dd, w1 = __int_as_float(p1.y) * dd;
        float w2 = __int_as_float(p2.y) * dd, w3 = __int_as_float(p3.y) * dd;
        float4 v0 = ld_row_h(T, p0.x, lane);
        float4 v1 = ld_row_h(T, p1.x, lane);
        float4 v2 = ld_row_h(T, p2.x, lane);
        float4 v3 = ld_row_h(T, p3.x, lane);
        acc.x = fmaf(w0, v0.x, fmaf(w1, v1.x, fmaf(w2, v2.x, fmaf(w3, v3.x, acc.x))));
        acc.y = fmaf(w0, v0.y, fmaf(w1, v1.y, fmaf(w2, v2.y, fmaf(w3, v3.y, acc.y))));
        acc.z = fmaf(w0, v0.z, fmaf(w1, v1.z, fmaf(w2, v2.z, fmaf(w3, v3.z, acc.z))));
        acc.w = fmaf(w0, v0.w, fmaf(w1, v1.w, fmaf(w2, v2.w, fmaf(w3, v3.w, acc.w))));
    }
    for (; e < end; e++) {
        int2 p0 = g_csr2[e];
        float w0 = __int_as_float(p0.y) * dd;
        float4 v0 = ld_row_h(T, p0.x, lane);
        acc.x = fmaf(w0, v0.x, acc.x);
        acc.y = fmaf(w0, v0.y, acc.y);
        acc.z = fmaf(w0, v0.z, acc.z);
        acc.w = fmaf(w0, v0.w, acc.w);
    }

    float4 b = *(const float4*)&bias[lane * 4];
    float4 r;
    r.x = elu1(acc.x + b.x);
    r.y = elu1(acc.y + b.y);
    r.z = elu1(acc.z + b.z);
    r.w = elu1(acc.w + b.w);

    if (FUSE_FINAL) {
        float4 w = *(const float4*)&Wl[lane * 4];
        float s = r.x * w.x + r.y * w.y + r.z * w.z + r.w * w.w;
        #pragma unroll
        for (int d = 16; d; d >>= 1) s += __shfl_xor_sync(0xffffffffu, s, d);
        if (lane == 0) out[node] = s + bl[0];
    } else {
        uint2 st;
        __half2 h0 = __floats2half2_rn(r.x, r.y);
        __half2 h1 = __floats2half2_rn(r.z, r.w);
        st.x = *(uint32_t*)&h0;
        st.y = *(uint32_t*)&h1;
        *(uint2*)&Hout[node * FEAT + lane * 4] = st;
    }
}

// ================= launch =================
extern "C" void kernel_launch(void* const* d_in, const int* in_sizes, int n_in,
                              void* d_out, int out_size) {
    const float* x  = (const float*)d_in[0];
    const float* Ws = (const float*)d_in[1];
    const float* bs = (const float*)d_in[2];
    const float* Wl = (const float*)d_in[3];
    const float* bl = (const float*)d_in[4];
    const int*   ei = (const int*)d_in[5];
    const int E = in_sizes[5] / 2;
    const int* src = ei;
    const int* dst = ei + E;
    float* out = (float*)d_out;

    __half *hbuf = nullptr, *tbuf = nullptr, *xh = nullptr;
    void *degp = nullptr, *tsp = nullptr;
    cudaGetSymbolAddress((void**)&hbuf, g_bufH);
    cudaGetSymbolAddress((void**)&tbuf, g_bufT);
    cudaGetSymbolAddress((void**)&xh, g_xh);
    cudaGetSymbolAddress(&degp, g_deg);
    cudaGetSymbolAddress(&tsp, g_tilestate);

    // graph structure + input conversion
    cudaMemsetAsync(degp, 0, N_NODES * sizeof(int), 0);
    cudaMemsetAsync(tsp, 0, SCAN_NT * sizeof(unsigned long long), 0);
    k_x2h<<<(N_NODES * FEAT / 8 + 255) / 256, 256>>>(x, xh, N_NODES * FEAT);
    k_count<<<(E / 4 + 255) / 256, 256>>>(dst, E);
    k_scan_dl<<<SCAN_NT, 1024>>>();
    k_fill<<<(E / 4 + 255) / 256, 256>>>(src, dst, E);

    const int ntiles = (N_NODES + 127) / 128;   // 391
    const int nagg   = (N_NODES + 7) / 8;

    // layer 1 (fp16 x)
    k_gemm_h<<<ntiles, 256>>>(xh, Ws, tbuf, N_NODES);
    k_agg_t<0><<<nagg, 256>>>(tbuf, bs, hbuf, nullptr, nullptr, nullptr);
    // layer 2
    k_gemm_h<<<ntiles, 256>>>(hbuf, Ws + FEAT * FEAT, tbuf, N_NODES);
    k_agg_t<0><<<nagg, 256>>>(tbuf, bs + FEAT, hbuf, nullptr, nullptr, nullptr);
    // layer 3 + fused final projection
    k_gemm_h<<<ntiles, 256>>>(hbuf, Ws + 2 * FEAT * FEAT, tbuf, N_NODES);
    k_agg_t<1><<<nagg, 256>>>(tbuf, bs + 2 * FEAT, nullptr, Wl, bl, out);
}

// round 13
// speedup vs baseline: 1.0116x; 1.0116x over previous
#include <cuda_runtime.h>
#include <cuda_fp16.h>
#include <math.h>
#include <stdint.h>

#define N_NODES 50000
#define FEAT    128
#define MAX_E   800000
#define SCAN_TILE 4096
#define SCAN_NT ((N_NODES + SCAN_TILE - 1) / SCAN_TILE)   // 13

// ---- scratch (static __device__ arrays; no runtime allocation) ----
__device__ __half g_bufT[N_NODES * FEAT];   // post-GEMM features (fp16)
__device__ __half g_bufH[N_NODES * FEAT];   // post-agg features (fp16)
__device__ __half g_xh[N_NODES * FEAT];     // fp16 copy of input x
__device__ int   g_deg[N_NODES];
__device__ float g_dis[N_NODES];
__device__ int   g_rowoff[N_NODES + 1];
__device__ int   g_rank[MAX_E];             // per-edge rank within its dst list
__device__ int2  g_csr2[MAX_E];             // (src, dis[src]) per edge
__device__ unsigned long long g_tilestate[SCAN_NT];

// ================= GEMM pieces =================
#define WROW 72

__device__ __forceinline__ uint32_t pack_h2(__half a, __half b) {
    __half2 h = __halves2half2(a, b);
    return *(uint32_t*)&h;
}
__device__ __forceinline__ void mma_f16(float* c, const uint32_t* a, uint32_t b0, uint32_t b1) {
    asm volatile(
        "mma.sync.aligned.m16n8k16.row.col.f32.f16.f16.f32 "
        "{%0,%1,%2,%3}, {%4,%5,%6,%7}, {%8,%9}, {%0,%1,%2,%3};"
        : "+f"(c[0]), "+f"(c[1]), "+f"(c[2]), "+f"(c[3])
        : "r"(a[0]), "r"(a[1]), "r"(a[2]), "r"(a[3]), "r"(b0), "r"(b1));
}
__device__ __forceinline__ void stage_W(uint32_t* Wh, const float* __restrict__ W, int tid) {
    for (int idx = tid; idx < 64 * 128; idx += 256) {
        int p = idx >> 7, n = idx & 127;
        int k = p * 2;
        float w0 = W[k * FEAT + n];
        float w1 = W[(k + 1) * FEAT + n];
        int kstep = p >> 3, q = p & 7;
        int word = n * WROW + kstep * 8 + (q & 3) * 2 + (q >> 2);
        Wh[word] = pack_h2(__float2half_rn(w0), __float2half_rn(w1));
    }
}

// round-11 proven mainloop: per-kstep A loads, single MMA pass (fp16 A)
__device__ __forceinline__ void gemm_body(uint32_t* Wh, const __half* __restrict__ A,
                                          const float* __restrict__ W,
                                          __half* __restrict__ C, int nrows, int tile) {
    int tid = threadIdx.x, wid = tid >> 5, lane = tid & 31;
    int g = lane >> 2, t = lane & 3;
    stage_W(Wh, W, tid);
    __syncthreads();

    int r0 = tile * 128 + wid * 16 + g;
    int r1 = r0 + 8;
    bool v0 = r0 < nrows, v1 = r1 < nrows;

    float acc[16][4];
    #pragma unroll
    for (int n0 = 0; n0 < 16; n0++)
        #pragma unroll
        for (int j = 0; j < 4; j++) acc[n0][j] = 0.0f;

    #pragma unroll
    for (int kstep = 0; kstep < 8; kstep++) {
        int ka = kstep * 16 + 2 * t;
        uint32_t a[4];
        a[0] = v0 ? *(const uint32_t*)&A[r0 * FEAT + ka]     : 0u;
        a[1] = v1 ? *(const uint32_t*)&A[r1 * FEAT + ka]     : 0u;
        a[2] = v0 ? *(const uint32_t*)&A[r0 * FEAT + ka + 8] : 0u;
        a[3] = v1 ? *(const uint32_t*)&A[r1 * FEAT + ka + 8] : 0u;

        int bword = g * WROW + kstep * 8 + t * 2;
        #pragma unroll
        for (int n0 = 0; n0 < 16; n0++) {
            uint2 bh = *(const uint2*)&Wh[n0 * 8 * WROW + bword];
            mma_f16(acc[n0], a, bh.x, bh.y);
        }
    }

    #pragma unroll
    for (int n0 = 0; n0 < 16; n0++) {
        int col = n0 * 8 + 2 * t;
        if (v0) *(__half2*)&C[r0 * FEAT + col] = __floats2half2_rn(acc[n0][0], acc[n0][1]);
        if (v1) *(__half2*)&C[r1 * FEAT + col] = __floats2half2_rn(acc[n0][2], acc[n0][3]);
    }
}

// ================= setup bodies =================
// count: 8 edges/thread, record rank
__device__ __forceinline__ void count_body(const int* __restrict__ dst, int E, int bid) {
    int i = (bid * 256 + threadIdx.x) * 8;
    if (i + 7 < E) {
        int4 d0 = *(const int4*)&dst[i];
        int4 d1 = *(const int4*)&dst[i + 4];
        int4 r0, r1;
        r0.x = atomicAdd(&g_deg[d0.x], 1);
        r0.y = atomicAdd(&g_deg[d0.y], 1);
        r0.z = atomicAdd(&g_deg[d0.z], 1);
        r0.w = atomicAdd(&g_deg[d0.w], 1);
        r1.x = atomicAdd(&g_deg[d1.x], 1);
        r1.y = atomicAdd(&g_deg[d1.y], 1);
        r1.z = atomicAdd(&g_deg[d1.z], 1);
        r1.w = atomicAdd(&g_deg[d1.w], 1);
        *(int4*)&g_rank[i]     = r0;
        *(int4*)&g_rank[i + 4] = r1;
    } else {
        for (int j = i; j < E; j++) g_rank[j] = atomicAdd(&g_deg[dst[j]], 1);
    }
}

// x -> fp16 (8 floats/thread)
__device__ __forceinline__ void x2h_body(const float* __restrict__ x, __half* __restrict__ xh,
                                         int n, int bid) {
    int i = (bid * 256 + threadIdx.x) * 8;
    if (i + 7 < n) {
        float4 f0 = *(const float4*)&x[i];
        float4 f1 = *(const float4*)&x[i + 4];
        uint4 o;
        __half2 h0 = __floats2half2_rn(f0.x, f0.y);
        __half2 h1 = __floats2half2_rn(f0.z, f0.w);
        __half2 h2 = __floats2half2_rn(f1.x, f1.y);
        __half2 h3 = __floats2half2_rn(f1.z, f1.w);
        o.x = *(uint32_t*)&h0; o.y = *(uint32_t*)&h1;
        o.z = *(uint32_t*)&h2; o.w = *(uint32_t*)&h3;
        *(uint4*)&xh[i] = o;
    }
}

// fill: 8 edges/thread, no atomics
__device__ __forceinline__ void fill_body(const int* __restrict__ src,
                                          const int* __restrict__ dst, int E, int bid) {
    int i = (bid * 256 + threadIdx.x) * 8;
    if (i + 7 < E) {
        int4 s0 = *(const int4*)&src[i];
        int4 s1 = *(const int4*)&src[i + 4];
        int4 d0 = *(const int4*)&dst[i];
        int4 d1 = *(const int4*)&dst[i + 4];
        int4 r0 = *(const int4*)&g_rank[i];
        int4 r1 = *(const int4*)&g_rank[i + 4];
        float f0 = g_dis[s0.x], f1 = g_dis[s0.y], f2 = g_dis[s0.z], f3 = g_dis[s0.w];
        float f4 = g_dis[s1.x], f5 = g_dis[s1.y], f6 = g_dis[s1.z], f7 = g_dis[s1.w];
        g_csr2[g_rowoff[d0.x] + r0.x] = make_int2(s0.x, __float_as_int(f0));
        g_csr2[g_rowoff[d0.y] + r0.y] = make_int2(s0.y, __float_as_int(f1));
        g_csr2[g_rowoff[d0.z] + r0.z] = make_int2(s0.z, __float_as_int(f2));
        g_csr2[g_rowoff[d0.w] + r0.w] = make_int2(s0.w, __float_as_int(f3));
        g_csr2[g_rowoff[d1.x] + r1.x] = make_int2(s1.x, __float_as_int(f4));
        g_csr2[g_rowoff[d1.y] + r1.y] = make_int2(s1.y, __float_as_int(f5));
        g_csr2[g_rowoff[d1.z] + r1.z] = make_int2(s1.z, __float_as_int(f6));
        g_csr2[g_rowoff[d1.w] + r1.w] = make_int2(s1.w, __float_as_int(f7));
    } else {
        for (int j = i; j < E; j++) {
            int sj = src[j];
            g_csr2[g_rowoff[dst[j]] + g_rank[j]] = make_int2(sj, __float_as_int(g_dis[sj]));
        }
    }
}

// ================= merged kernels =================
// setup1: blocks [0, nCount) do count; rest do x2h
__global__ __launch_bounds__(256) void k_setup1(const int* __restrict__ dst, int E,
                                                const float* __restrict__ x,
                                                __half* __restrict__ xh, int n, int nCount) {
    int bid = blockIdx.x;
    if (bid < nCount) count_body(dst, E, bid);
    else              x2h_body(x, xh, n, bid - nCount);
}

// fill+gemm1: blocks [0, ntiles) do GEMM layer-1; rest do fill
__global__ __launch_bounds__(256) void k_fillgemm1(const int* __restrict__ src,
                                                   const int* __restrict__ dst, int E,
                                                   const __half* __restrict__ A,
                                                   const float* __restrict__ W,
                                                   __half* __restrict__ C,
                                                   int nrows, int ntiles) {
    __shared__ uint32_t Wh[128 * WROW];
    int bid = blockIdx.x;
    if (bid < ntiles) gemm_body(Wh, A, W, C, nrows, bid);
    else              fill_body(src, dst, E, bid - ntiles);
}

// standalone GEMM for layers 2,3
__global__ __launch_bounds__(256) void k_gemm_h(const __half* __restrict__ A,
                                                const float* __restrict__ W,
                                                __half* __restrict__ C, int nrows) {
    __shared__ uint32_t Wh[128 * WROW];
    gemm_body(Wh, A, W, C, nrows, blockIdx.x);
}

// ================= scan =================
// decoupled-lookback scan: rowoff = exclusive scan of deg; also dis = rsqrt(deg+1)
__global__ __launch_bounds__(1024) void k_scan_dl() {
    __shared__ int sh_w[32];
    __shared__ unsigned int sh_prefix;
    int tid = threadIdx.x, lane = tid & 31, wid = tid >> 5;
    int tile = blockIdx.x;
    int i0 = tile * SCAN_TILE + tid * 4;

    int4 v = make_int4(0, 0, 0, 0);
    if (i0 < N_NODES) {
        v = *(const int4*)&g_deg[i0];
        float4 d;
        d.x = rsqrtf((float)(v.x + 1));
        d.y = rsqrtf((float)(v.y + 1));
        d.z = rsqrtf((float)(v.z + 1));
        d.w = rsqrtf((float)(v.w + 1));
        *(float4*)&g_dis[i0] = d;
    }
    int t0 = v.x, t1 = t0 + v.y, t2 = t1 + v.z, t3 = t2 + v.w;
    int sc = t3;
    #pragma unroll
    for (int d = 1; d < 32; d <<= 1) {
        int t = __shfl_up_sync(0xffffffffu, sc, d);
        if (lane >= d) sc += t;
    }
    if (lane == 31) sh_w[wid] = sc;
    __syncthreads();
    if (wid == 0) {
        int ws = sh_w[lane];
        #pragma unroll
        for (int d = 1; d < 32; d <<= 1) {
            int t = __shfl_up_sync(0xffffffffu, ws, d);
            if (lane >= d) ws += t;
        }
        sh_w[lane] = ws;
    }
    __syncthreads();
    int total = sh_w[31];
    int thr_excl = (wid ? sh_w[wid - 1] : 0) + sc - t3;

    if (tid == 0) {
        unsigned long long st = ((tile == 0) ? (2ULL << 32) : (1ULL << 32)) | (unsigned)total;
        atomicExch(&g_tilestate[tile], st);
    }
    if (wid == 0) {
        unsigned int prefix = 0;
        if (tile > 0) {
            bool have = lane < tile;
            unsigned long long s = 0;
            if (have) {
                do { s = *(volatile unsigned long long*)&g_tilestate[tile - 1 - lane]; }
                while ((unsigned)(s >> 32) == 0u);
            }
            unsigned flag = (unsigned)(s >> 32);
            unsigned mask = __ballot_sync(0xffffffffu, have && flag == 2u);
            int firstInc = __ffs(mask) - 1;   // exists: tile 0 is always INCLUSIVE
            unsigned contrib = (have && lane <= firstInc) ? (unsigned)s : 0u;
            #pragma unroll
            for (int d = 16; d; d >>= 1) contrib += __shfl_xor_sync(0xffffffffu, contrib, d);
            prefix = contrib;
            if (lane == 0)
                atomicExch(&g_tilestate[tile], (2ULL << 32) | (unsigned)(prefix + (unsigned)total));
        }
        if (lane == 0) sh_prefix = prefix;
    }
    __syncthreads();
    int base = (int)sh_prefix + thr_excl;
    if (i0 < N_NODES) {
        int4 o = make_int4(base, base + t0, base + t1, base + t2);
        *(int4*)&g_rowoff[i0] = o;
    }
    if (tile == SCAN_NT - 1 && tid == 0) g_rowoff[N_NODES] = (int)sh_prefix + total;
}

// ================= aggregation (one warp per dst node, packed CSR) =======
__device__ __forceinline__ float elu1(float v) { return v > 0.0f ? v : expm1f(v); }

__device__ __forceinline__ float4 ld_row_h(const __half* __restrict__ T, int s, int lane) {
    uint2 u = *(const uint2*)(T + s * FEAT + lane * 4);
    __half2 h0 = *(__half2*)&u.x;
    __half2 h1 = *(__half2*)&u.y;
    float2 f0 = __half22float2(h0);
    float2 f1 = __half22float2(h1);
    return make_float4(f0.x, f0.y, f1.x, f1.y);
}

// FUSE_FINAL=0: Hout = fp16(ELU(acc+bias)). FUSE_FINAL=1: out = ELU(acc+bias)@Wl + bl.
template<int FUSE_FINAL>
__global__ __launch_bounds__(256) void k_agg_t(const __half* __restrict__ T,
                                               const float* __restrict__ bias,
                                               __half* __restrict__ Hout,
                                               const float* __restrict__ Wl,
                                               const float* __restrict__ bl,
                                               float* __restrict__ out) {
    int warp = (int)((blockIdx.x * blockDim.x + threadIdx.x) >> 5);
    int lane = threadIdx.x & 31;
    if (warp >= N_NODES) return;
    int node = warp;
    float dd = g_dis[node];

    float4 acc = ld_row_h(T, node, lane);
    float ws = dd * dd;                        // self-loop weight
    acc.x *= ws; acc.y *= ws; acc.z *= ws; acc.w *= ws;

    int beg = g_rowoff[node];
    int end = g_rowoff[node + 1];
    int e = beg;
    for (; e + 3 < end; e += 4) {
        int2 p0 = g_csr2[e],     p1 = g_csr2[e + 1];
        int2 p2 = g_csr2[e + 2], p3 = g_csr2[e + 3];
        float w0 = __int_as_float(p0.y) * dd, w1 = __int_as_float(p1.y) * dd;
        float w2 = __int_as_float(p2.y) * dd, w3 = __int_as_float(p3.y) * dd;
        float4 v0 = ld_row_h(T, p0.x, lane);
        float4 v1 = ld_row_h(T, p1.x, lane);
        float4 v2 = ld_row_h(T, p2.x, lane);
        float4 v3 = ld_row_h(T, p3.x, lane);
        acc.x = fmaf(w0, v0.x, fmaf(w1, v1.x, fmaf(w2, v2.x, fmaf(w3, v3.x, acc.x))));
        acc.y = fmaf(w0, v0.y, fmaf(w1, v1.y, fmaf(w2, v2.y, fmaf(w3, v3.y, acc.y))));
        acc.z = fmaf(w0, v0.z, fmaf(w1, v1.z, fmaf(w2, v2.z, fmaf(w3, v3.z, acc.z))));
        acc.w = fmaf(w0, v0.w, fmaf(w1, v1.w, fmaf(w2, v2.w, fmaf(w3, v3.w, acc.w))));
    }
    for (; e < end; e++) {
        int2 p0 = g_csr2[e];
        float w0 = __int_as_float(p0.y) * dd;
        float4 v0 = ld_row_h(T, p0.x, lane);
        acc.x = fmaf(w0, v0.x, acc.x);
        acc.y = fmaf(w0, v0.y, acc.y);
        acc.z = fmaf(w0, v0.z, acc.z);
        acc.w = fmaf(w0, v0.w, acc.w);
    }

    float4 b = *(const float4*)&bias[lane * 4];
    float4 r;
    r.x = elu1(acc.x + b.x);
    r.y = elu1(acc.y + b.y);
    r.z = elu1(acc.z + b.z);
    r.w = elu1(acc.w + b.w);

    if (FUSE_FINAL) {
        float4 w = *(const float4*)&Wl[lane * 4];
        float s = r.x * w.x + r.y * w.y + r.z * w.z + r.w * w.w;
        #pragma unroll
        for (int d = 16; d; d >>= 1) s += __shfl_xor_sync(0xffffffffu, s, d);
        if (lane == 0) out[node] = s + bl[0];
    } else {
        uint2 st;
        __half2 h0 = __floats2half2_rn(r.x, r.y);
        __half2 h1 = __floats2half2_rn(r.z, r.w);
        st.x = *(uint32_t*)&h0;
        st.y = *(uint32_t*)&h1;
        *(uint2*)&Hout[node * FEAT + lane * 4] = st;
    }
}

// ================= launch =================
extern "C" void kernel_launch(void* const* d_in, const int* in_sizes, int n_in,
                              void* d_out, int out_size) {
    const float* x  = (const float*)d_in[0];
    const float* Ws = (const float*)d_in[1];
    const float* bs = (const float*)d_in[2];
    const float* Wl = (const float*)d_in[3];
    const float* bl = (const float*)d_in[4];
    const int*   ei = (const int*)d_in[5];
    const int E = in_sizes[5] / 2;
    const int* src = ei;
    const int* dst = ei + E;
    float* out = (float*)d_out;

    __half *hbuf = nullptr, *tbuf = nullptr, *xh = nullptr;
    void *degp = nullptr, *tsp = nullptr;
    cudaGetSymbolAddress((void**)&hbuf, g_bufH);
    cudaGetSymbolAddress((void**)&tbuf, g_bufT);
    cudaGetSymbolAddress((void**)&xh, g_xh);
    cudaGetSymbolAddress(&degp, g_deg);
    cudaGetSymbolAddress(&tsp, g_tilestate);

    cudaMemsetAsync(degp, 0, N_NODES * sizeof(int), 0);
    cudaMemsetAsync(tsp, 0, SCAN_NT * sizeof(unsigned long long), 0);

    const int nX = N_NODES * FEAT;
    const int nCount = (E / 8 + 255) / 256;          // 391
    const int nX2h   = (nX / 8 + 255) / 256;         // 3125
    const int ntiles = (N_NODES + 127) / 128;        // 391
    const int nFill  = (E / 8 + 255) / 256;          // 391
    const int nagg   = (N_NODES + 7) / 8;

    // setup phase 1: degree count (+rank) and x->fp16, concurrent
    k_setup1<<<nCount + nX2h, 256>>>(dst, E, x, xh, nX, nCount);
    // scan: rowoff + dis
    k_scan_dl<<<SCAN_NT, 1024>>>();
    // CSR fill and layer-1 GEMM, concurrent
    k_fillgemm1<<<ntiles + nFill, 256>>>(src, dst, E, xh, Ws, tbuf, N_NODES, ntiles);
    k_agg_t<0><<<nagg, 256>>>(tbuf, bs, hbuf, nullptr, nullptr, nullptr);
    // layer 2
    k_gemm_h<<<ntiles, 256>>>(hbuf, Ws + FEAT * FEAT, tbuf, N_NODES);
    k_agg_t<0><<<nagg, 256>>>(tbuf, bs + FEAT, hbuf, nullptr, nullptr, nullptr);
    // layer 3 + fused final projection
    k_gemm_h<<<ntiles, 256>>>(hbuf, Ws + 2 * FEAT * FEAT, tbuf, N_NODES);
    k_agg_t<1><<<nagg, 256>>>(tbuf, bs + 2 * FEAT, nullptr, Wl, bl, out);
}